// round 14
// baseline (speedup 1.0000x reference)
#include <cuda_runtime.h>
#include <cuda_bf16.h>
#include <cuda_fp16.h>
#include <cstdint>

#define CC    1280
#define SCTX  3072
#define NROWS 10240

// ---------------- scratch (static device globals; no allocation) ----------------
__device__ __nv_bfloat16 g_X[(size_t)NROWS * CC];     // bf16 hs
__device__ __half        g_Q[(size_t)NROWS * CC];     // fp16, pre-scaled by 0.125*log2(e)
__device__ __half        g_K[(size_t)NROWS * CC];     // fp16
__device__ __half        g_V[(size_t)NROWS * CC];     // fp16
__device__ __nv_bfloat16 g_O[(size_t)NROWS * CC];     // attn output (bf16 for out-proj)
__device__ __nv_bfloat16 g_WT[4 * (size_t)CC * CC];   // WT[z][n][k] = W_z[k][n]
__device__ int g_ctx[10 * SCTX];

#define QSCALE 0.18033688011112042f   // 0.125 * log2(e), folded into Q projection

// ---------------- helpers ----------------
__device__ __forceinline__ unsigned bf16x2(float hi, float lo) {
    unsigned r; asm("cvt.rn.bf16x2.f32 %0, %1, %2;" : "=r"(r) : "f"(hi), "f"(lo)); return r;
}
__device__ __forceinline__ unsigned f16x2(float hi, float lo) {
    unsigned r; asm("cvt.rn.f16x2.f32 %0, %1, %2;" : "=r"(r) : "f"(hi), "f"(lo)); return r;
}
__device__ __forceinline__ unsigned ex2h2(unsigned x) {   // packed 2^x on f16x2
    unsigned r; asm("ex2.approx.f16x2 %0, %1;" : "=r"(r) : "r"(x)); return r;
}
// bf16 mma, f32 accum (GEMMs)
__device__ __forceinline__ void mma16(float* d, const unsigned* a, unsigned b0, unsigned b1) {
    asm("mma.sync.aligned.m16n8k16.row.col.f32.bf16.bf16.f32 "
        "{%0,%1,%2,%3},{%4,%5,%6,%7},{%8,%9},{%0,%1,%2,%3};"
        : "+f"(d[0]), "+f"(d[1]), "+f"(d[2]), "+f"(d[3])
        : "r"(a[0]), "r"(a[1]), "r"(a[2]), "r"(a[3]), "r"(b0), "r"(b1));
}
// f16 mma, f16 accum (attention S-phase)
__device__ __forceinline__ void mma16h(unsigned* d, const unsigned* a, unsigned b0, unsigned b1) {
    asm("mma.sync.aligned.m16n8k16.row.col.f16.f16.f16.f16 "
        "{%0,%1},{%2,%3,%4,%5},{%6,%7},{%0,%1};"
        : "+r"(d[0]), "+r"(d[1])
        : "r"(a[0]), "r"(a[1]), "r"(a[2]), "r"(a[3]), "r"(b0), "r"(b1));
}
// f16 mma, f32 accum (attention PV)
__device__ __forceinline__ void mma16f(float* d, const unsigned* a, unsigned b0, unsigned b1) {
    asm("mma.sync.aligned.m16n8k16.row.col.f32.f16.f16.f32 "
        "{%0,%1,%2,%3},{%4,%5,%6,%7},{%8,%9},{%0,%1,%2,%3};"
        : "+f"(d[0]), "+f"(d[1]), "+f"(d[2]), "+f"(d[3])
        : "r"(a[0]), "r"(a[1]), "r"(a[2]), "r"(a[3]), "r"(b0), "r"(b1));
}
__device__ __forceinline__ void ldmx4(unsigned* r, unsigned addr) {
    asm volatile("ldmatrix.sync.aligned.m8n8.x4.shared.b16 {%0,%1,%2,%3}, [%4];"
        : "=r"(r[0]), "=r"(r[1]), "=r"(r[2]), "=r"(r[3]) : "r"(addr));
}
__device__ __forceinline__ void ldmx4t(unsigned* r, unsigned addr) {
    asm volatile("ldmatrix.sync.aligned.m8n8.x4.trans.shared.b16 {%0,%1,%2,%3}, [%4];"
        : "=r"(r[0]), "=r"(r[1]), "=r"(r[2]), "=r"(r[3]) : "r"(addr));
}
__device__ __forceinline__ void cp16s(unsigned s, const void* g) {
    asm volatile("cp.async.cg.shared.global [%0], [%1], 16;" :: "r"(s), "l"(g));
}
__device__ __forceinline__ void cp_commit() { asm volatile("cp.async.commit_group;"); }
__device__ __forceinline__ void cp_wait1()  { asm volatile("cp.async.wait_group 1;"); }
__device__ __forceinline__ void cp_wait0()  { asm volatile("cp.async.wait_group 0;"); }

// swizzled dst offset within a tile of 128B rows: chunk c (16B), row r
__device__ __forceinline__ unsigned swz(int r, int c) {
    return (unsigned)(r * 128 + ((c ^ (r & 7)) * 16));
}

// ---------------- prepasses ----------------
__global__ void cvt_hs_kernel(const float4* __restrict__ in) {
    int i = blockIdx.x * blockDim.x + threadIdx.x;   // over NROWS*CC/4
    float4 f = in[i];
    ((uint2*)g_X)[i] = make_uint2(bf16x2(f.y, f.x), bf16x2(f.w, f.z));
}

__global__ void build_ctx_kernel(const int* __restrict__ indices) {
    int bi = blockIdx.x;            // bi = s*5 + i
    int i  = bi % 5;
    int s  = bi / 5;
    for (int k = threadIdx.x; k < SCTX; k += blockDim.x) {
        int row;
        if (k < 2048) {
            int jp = k >> 9;
            int j  = jp + (jp >= i ? 1 : 0);
            row = (s * 5 + j) * 1024 + indices[j * 512 + (k & 511)];
        } else {
            row = bi * 1024 + (k - 2048);
        }
        g_ctx[bi * SCTX + k] = row;
    }
}

__global__ void transpose_kernel(const float* __restrict__ W0, const float* __restrict__ W1,
                                 const float* __restrict__ W2, const float* __restrict__ W3) {
    __shared__ float t[32][33];
    const int z = blockIdx.z;
    const float* src = z == 0 ? W0 : z == 1 ? W1 : z == 2 ? W2 : W3;
    __nv_bfloat16* dst = g_WT + (size_t)z * CC * CC;
    const int col  = blockIdx.x * 32 + threadIdx.x;
    const int row0 = blockIdx.y * 32;
    #pragma unroll
    for (int i = 0; i < 4; ++i)
        t[threadIdx.y + i * 8][threadIdx.x] = src[(size_t)(row0 + threadIdx.y + i * 8) * CC + col];
    __syncthreads();
    const int k = row0 + threadIdx.x;
    #pragma unroll
    for (int i = 0; i < 4; ++i)
        dst[(size_t)(blockIdx.x * 32 + threadIdx.y + i * 8) * CC + k] =
            __float2bfloat16(t[threadIdx.x][threadIdx.y + i * 8]);
}

// ---------------- bf16 mma GEMM: Y[M,N] = A[M,:] . WT[N,:]^T ----------------
// BM=128, BN=128, BK=64 (128B rows, SW128); 8 warps (4m x 2n), warp tile 32x64;
// 3-stage cp.async ring, one barrier per iteration; ldmatrix fragment loads.
// MODE 0 = f32 + bias + residual; MODE 1 = fp16 out.
static constexpr int GEMM_SMEM = 3 * 2 * 128 * 128;   // 98304 B

template<int MODE>
__device__ __forceinline__ void gemm_body(const __nv_bfloat16* __restrict__ A,
                                          const __nv_bfloat16* __restrict__ Bt,
                                          float* __restrict__ Yf,
                                          __half* __restrict__ Yh,
                                          const float* __restrict__ bias,
                                          const float* __restrict__ res,
                                          float scale) {
    extern __shared__ __align__(16) char smc[];
    const unsigned sbase = (unsigned)__cvta_generic_to_shared(smc);
    const int tid = threadIdx.x, lane = tid & 31, wid = tid >> 5;
    const int wm = wid >> 1, wn = wid & 1;
    const int lg = lane >> 2, lc = lane & 3;
    const int m0 = blockIdx.y << 7, n0 = blockIdx.x << 7;

    float acc[2][8][4];
    #pragma unroll
    for (int mt = 0; mt < 2; ++mt)
        #pragma unroll
        for (int nt = 0; nt < 8; ++nt)
            #pragma unroll
            for (int q = 0; q < 4; ++q) acc[mt][nt][q] = 0.f;

    auto load = [&](int buf, int k0) {   // k0 in bf16 elems
        const unsigned sA = sbase + (unsigned)buf * 32768u;
        const unsigned sB = sA + 16384u;
        #pragma unroll
        for (int i = 0; i < 4; ++i) {
            const int idx = tid + i * 256;
            const int row = idx >> 3, c = idx & 7;
            const unsigned so = swz(row, c);
            cp16s(sA + so, A  + (size_t)(m0 + row) * CC + k0 + c * 8);
            cp16s(sB + so, Bt + (size_t)(n0 + row) * CC + k0 + c * 8);
        }
        cp_commit();
    };

    load(0, 0);
    load(1, 64);

    // per-warp fragment address components
    const int arow = wm * 32 + (lane & 15);
    const int ach  = lane >> 4;
    const int brow = wn * 64 + ((lane >> 4) << 3) + (lane & 7);
    const int bch  = (lane >> 3) & 1;

    for (int it = 0; it < 20; ++it) {
        const int b = it % 3;
        if (it == 19) cp_wait0(); else cp_wait1();
        __syncthreads();                       // stage it ready; buffer (it+2)%3 free
        if (it + 2 < 20) load((it + 2) % 3, (it + 2) * 64);
        const unsigned aB = sbase + (unsigned)b * 32768u;
        const unsigned bB = aB + 16384u;
        #pragma unroll
        for (int ks = 0; ks < 4; ++ks) {
            unsigned af[2][4], bf[4][4];
            #pragma unroll
            for (int mt = 0; mt < 2; ++mt)
                ldmx4(af[mt], aB + swz(arow + mt * 16, 2 * ks + ach));
            #pragma unroll
            for (int g = 0; g < 4; ++g)
                ldmx4(bf[g], bB + swz(brow + g * 16, 2 * ks + bch));
            #pragma unroll
            for (int mt = 0; mt < 2; ++mt)
                #pragma unroll
                for (int g = 0; g < 4; ++g) {
                    mma16(acc[mt][2 * g],     af[mt], bf[g][0], bf[g][1]);
                    mma16(acc[mt][2 * g + 1], af[mt], bf[g][2], bf[g][3]);
                }
        }
    }

    #pragma unroll
    for (int mt = 0; mt < 2; ++mt) {
        const int r0 = m0 + wm * 32 + mt * 16 + lg;
        #pragma unroll
        for (int nt = 0; nt < 8; ++nt) {
            const int n = n0 + wn * 64 + nt * 8 + 2 * lc;
            float v0 = acc[mt][nt][0] * scale, v1 = acc[mt][nt][1] * scale;
            float v2 = acc[mt][nt][2] * scale, v3 = acc[mt][nt][3] * scale;
            if (MODE == 0) {
                const float2 b0 = *(const float2*)&bias[n];
                const float2 u0 = *(const float2*)&res[(size_t)r0 * CC + n];
                const float2 u1 = *(const float2*)&res[(size_t)(r0 + 8) * CC + n];
                *(float2*)&Yf[(size_t)r0 * CC + n]       = make_float2(v0 + b0.x + u0.x, v1 + b0.y + u0.y);
                *(float2*)&Yf[(size_t)(r0 + 8) * CC + n] = make_float2(v2 + b0.x + u1.x, v3 + b0.y + u1.y);
            } else {
                *(unsigned*)&Yh[(size_t)r0 * CC + n]       = f16x2(v1, v0);
                *(unsigned*)&Yh[(size_t)(r0 + 8) * CC + n] = f16x2(v3, v2);
            }
        }
    }
}

__global__ __launch_bounds__(256, 2) void gemm_qkv_kernel() {
    const int z = blockIdx.z;
    const __nv_bfloat16* WT = g_WT + (size_t)z * CC * CC;
    __half* Y = z == 0 ? g_Q : z == 1 ? g_K : g_V;
    // Q carries 0.125 * log2(e) so attention can use raw ex2
    gemm_body<1>(g_X, WT, nullptr, Y, nullptr, nullptr, z == 0 ? QSCALE : 1.0f);
}

__global__ __launch_bounds__(256, 2) void gemm_out_kernel(float* __restrict__ Y,
                                                          const float* __restrict__ bias,
                                                          const float* __restrict__ res) {
    gemm_body<0>((const __nv_bfloat16*)g_O, g_WT + 3 * (size_t)CC * CC, Y, nullptr, bias, res, 1.0f);
}

// ---------------- gathered flash attention: fp16 mma, fp16 S-accum ----------------
// grid (8 q-blocks, 20 heads, 10 (side,image)); 256 threads = 8 warps; warp: 16 q rows.
// BQ=128, BKEY=64, hd=64. 4-stage KV ring, two tiles per barrier.
// S-phase: f16 accum; logits in log2 domain; P = ex2.f16x2 on accum regs (zero cvts).
// Denominator via packed HADD2 on the (otherwise idle) fma pipe — NOT the tensor pipe;
// cross-lane reduce deferred to a single end-of-kernel shuffle pair.
static constexpr int ATTN_SMEM = (128 + 4 * 128) * 128;   // Q + 4*(K+V) = 81920 B

__global__ __launch_bounds__(256, 2) void attn_kernel() {
    extern __shared__ __align__(16) char smc[];
    const unsigned sQ   = (unsigned)__cvta_generic_to_shared(smc);
    const unsigned sKV0 = sQ + 16384u;        // stage s: K at +s*16384, V at +s*16384+8192

    const int tid = threadIdx.x, lane = tid & 31, wid = tid >> 5;
    const int lg = lane >> 2, lc = lane & 3;
    const int qb = blockIdx.x, h = blockIdx.y, bi = blockIdx.z;
    const int r0 = bi * 1024 + (qb << 7);
    const int hc = h << 6;
    const int* ctx = g_ctx + bi * SCTX;

    // Q tile load: 128 rows x 8 chunks; 2 threads/row, 4 chunks each
    {
        const int r = tid >> 1, c0 = (tid & 1) * 4;
        const __half* gq = g_Q + (size_t)(r0 + r) * CC + hc;
        #pragma unroll
        for (int j = 0; j < 4; ++j)
            cp16s(sQ + swz(r, c0 + j), gq + (c0 + j) * 8);
    }
    // K/V tile gather: 64 rows x 8 chunks; 4 threads/row, 2+2 chunks each
    auto loadKV = [&](int buf, int kt) {
        const unsigned kB = sKV0 + (unsigned)buf * 16384u;
        const unsigned vB = kB + 8192u;
        const int r = tid >> 2, c = tid & 3;
        const int krow = ctx[(kt << 6) + r];
        const size_t gb = (size_t)krow * CC + hc;
        cp16s(kB + swz(r, c),     g_K + gb + c * 8);
        cp16s(kB + swz(r, c + 4), g_K + gb + (c + 4) * 8);
        cp16s(vB + swz(r, c),     g_V + gb + c * 8);
        cp16s(vB + swz(r, c + 4), g_V + gb + (c + 4) * 8);
        cp_commit();
    };
    loadKV(0, 0);       // Q rides in group 0
    loadKV(1, 1);

    float oacc[8][4];
    #pragma unroll
    for (int nt = 0; nt < 8; ++nt)
        #pragma unroll
        for (int q = 0; q < 4; ++q) oacc[nt][q] = 0.f;
    float lsum0 = 0.f, lsum1 = 0.f;           // denominator partials (this lane's cols)
    unsigned qf[4][4];

    // fragment address components
    const int qrow = wid * 16 + (lane & 15);
    const int qch  = lane >> 4;
    const int krow = ((lane >> 4) << 3) + (lane & 7);
    const int kch  = (lane >> 3) & 1;
    const int vrow = ((lane >> 3) & 1) * 8 + (lane & 7);
    const int vch  = lane >> 4;

    // per-tile compute: S = Q@K^T (f16 accum), P = 2^S, denominator via HADD2, O += P@V
    auto tile_compute = [&](int buf) {
        const unsigned kB = sKV0 + (unsigned)buf * 16384u;
        const unsigned vB = kB + 8192u;

        // S accumulators: 8 n-blocks x 2 packed f16x2 regs
        unsigned s2[8][2];
        #pragma unroll
        for (int g = 0; g < 8; ++g) { s2[g][0] = 0u; s2[g][1] = 0u; }

        #pragma unroll
        for (int ks = 0; ks < 4; ++ks) {
            #pragma unroll
            for (int g = 0; g < 4; ++g) {
                unsigned kf[4];
                ldmx4(kf, kB + swz(g * 16 + krow, 2 * ks + kch));
                mma16h(s2[2 * g],     qf[ks], kf[0], kf[1]);
                mma16h(s2[2 * g + 1], qf[ks], kf[2], kf[3]);
            }
        }

        // P = 2^S directly on packed accumulator regs; layout already matches PV A-frags.
        // Row sums accumulate on the fma pipe (HADD2 tree), f32-converted once per tile.
        unsigned pf[4][4];
        __half2 hs0 = __float2half2_rn(0.f), hs1 = __float2half2_rn(0.f);
        #pragma unroll
        for (int s = 0; s < 4; ++s) {
            pf[s][0] = ex2h2(s2[2 * s][0]);
            pf[s][1] = ex2h2(s2[2 * s][1]);
            pf[s][2] = ex2h2(s2[2 * s + 1][0]);
            pf[s][3] = ex2h2(s2[2 * s + 1][1]);
            hs0 = __hadd2(hs0, __hadd2(*(__half2*)&pf[s][0], *(__half2*)&pf[s][2]));  // row lg
            hs1 = __hadd2(hs1, __hadd2(*(__half2*)&pf[s][1], *(__half2*)&pf[s][3]));  // row lg+8
        }
        lsum0 += __low2float(hs0) + __high2float(hs0);
        lsum1 += __low2float(hs1) + __high2float(hs1);

        // O += P @ V  (f16 inputs, f32 accum; warp: 16q x 64d, k = 64 keys)
        #pragma unroll
        for (int s = 0; s < 4; ++s) {
            #pragma unroll
            for (int g = 0; g < 4; ++g) {
                unsigned vf[4];
                ldmx4t(vf, vB + swz(s * 16 + vrow, 2 * g + vch));
                mma16f(oacc[2 * g],     pf[s], vf[0], vf[1]);
                mma16f(oacc[2 * g + 1], pf[s], vf[2], vf[3]);
            }
        }
    };

    // 24 iterations, 2 tiles each, ONE barrier per iteration.
    for (int j = 0; j < 24; ++j) {
        cp_wait0();
        __syncthreads();
        if (j == 0) {                     // Q arrived with tile 0 — hoist fragments once
            #pragma unroll
            for (int ks = 0; ks < 4; ++ks)
                ldmx4(qf[ks], sQ + swz(qrow, 2 * ks + qch));
        }
        if (j + 1 < 24) {
            loadKV((2 * j + 2) & 3, 2 * j + 2);
            loadKV((2 * j + 3) & 3, 2 * j + 3);
        }
        tile_compute((2 * j) & 3);
        tile_compute((2 * j + 1) & 3);
    }

    // ---- cross-lane denominator reduce (4 lanes per row), normalize, store bf16 ----
    #pragma unroll
    for (int d = 1; d < 4; d <<= 1) {
        lsum0 += __shfl_xor_sync(0xffffffffu, lsum0, d);
        lsum1 += __shfl_xor_sync(0xffffffffu, lsum1, d);
    }
    const float inv0 = 1.0f / lsum0, inv1 = 1.0f / lsum1;
    const int qr = r0 + wid * 16 + lg;
    #pragma unroll
    for (int nt = 0; nt < 8; ++nt) {
        const int n = hc + nt * 8 + 2 * lc;
        *(unsigned*)&g_O[(size_t)qr * CC + n] =
            bf16x2(oacc[nt][1] * inv0, oacc[nt][0] * inv0);
        *(unsigned*)&g_O[(size_t)(qr + 8) * CC + n] =
            bf16x2(oacc[nt][3] * inv1, oacc[nt][2] * inv1);
    }
}

// ---------------- launcher ----------------
extern "C" void kernel_launch(void* const* d_in, const int* in_sizes, int n_in,
                              void* d_out, int out_size) {
    const float* hs  = (const float*)d_in[0];
    const int*   idx = (const int*)  d_in[1];
    const float* Wq  = (const float*)d_in[2];
    const float* Wk  = (const float*)d_in[3];
    const float* Wv  = (const float*)d_in[4];
    const float* Wo  = (const float*)d_in[5];
    const float* bo  = (const float*)d_in[6];
    float* out = (float*)d_out;

    cudaFuncSetAttribute(gemm_qkv_kernel, cudaFuncAttributeMaxDynamicSharedMemorySize, GEMM_SMEM);
    cudaFuncSetAttribute(gemm_out_kernel, cudaFuncAttributeMaxDynamicSharedMemorySize, GEMM_SMEM);
    cudaFuncSetAttribute(attn_kernel,     cudaFuncAttributeMaxDynamicSharedMemorySize, ATTN_SMEM);

    cvt_hs_kernel<<<(NROWS * CC / 4) / 256, 256>>>((const float4*)hs);
    transpose_kernel<<<dim3(CC / 32, CC / 32, 4), dim3(32, 8)>>>(Wq, Wk, Wv, Wo);
    build_ctx_kernel<<<10, 256>>>(idx);

    gemm_qkv_kernel<<<dim3(CC / 128, NROWS / 128, 3), 256, GEMM_SMEM>>>();

    attn_kernel<<<dim3(8, 20, 10), 256, ATTN_SMEM>>>();

    gemm_out_kernel<<<dim3(CC / 128, NROWS / 128), 256, GEMM_SMEM>>>(out, bo, hs);
}

// round 15
// speedup vs baseline: 1.0103x; 1.0103x over previous
#include <cuda_runtime.h>
#include <cuda_bf16.h>
#include <cuda_fp16.h>
#include <cstdint>

#define CC    1280
#define SCTX  3072
#define NROWS 10240

// ---------------- scratch (static device globals; no allocation) ----------------
__device__ __nv_bfloat16 g_X[(size_t)NROWS * CC];     // bf16 hs
__device__ __half        g_Q[(size_t)NROWS * CC];     // fp16, pre-scaled by 0.125*log2(e)
__device__ __half        g_K[(size_t)NROWS * CC];     // fp16
__device__ __half        g_V[(size_t)NROWS * CC];     // fp16
__device__ __nv_bfloat16 g_O[(size_t)NROWS * CC];     // attn output (bf16 for out-proj)
__device__ __nv_bfloat16 g_WT[4 * (size_t)CC * CC];   // WT[z][n][k] = W_z[k][n]
__device__ int g_ctx[10 * SCTX];

#define QSCALE 0.18033688011112042f   // 0.125 * log2(e), folded into Q projection

// ---------------- helpers ----------------
__device__ __forceinline__ unsigned bf16x2(float hi, float lo) {
    unsigned r; asm("cvt.rn.bf16x2.f32 %0, %1, %2;" : "=r"(r) : "f"(hi), "f"(lo)); return r;
}
__device__ __forceinline__ unsigned f16x2(float hi, float lo) {
    unsigned r; asm("cvt.rn.f16x2.f32 %0, %1, %2;" : "=r"(r) : "f"(hi), "f"(lo)); return r;
}
__device__ __forceinline__ unsigned ex2h2(unsigned x) {   // packed 2^x on f16x2
    unsigned r; asm("ex2.approx.f16x2 %0, %1;" : "=r"(r) : "r"(x)); return r;
}
// bf16 mma, f32 accum (GEMMs)
__device__ __forceinline__ void mma16(float* d, const unsigned* a, unsigned b0, unsigned b1) {
    asm("mma.sync.aligned.m16n8k16.row.col.f32.bf16.bf16.f32 "
        "{%0,%1,%2,%3},{%4,%5,%6,%7},{%8,%9},{%0,%1,%2,%3};"
        : "+f"(d[0]), "+f"(d[1]), "+f"(d[2]), "+f"(d[3])
        : "r"(a[0]), "r"(a[1]), "r"(a[2]), "r"(a[3]), "r"(b0), "r"(b1));
}
// f16 mma, f16 accum (attention S-phase)
__device__ __forceinline__ void mma16h(unsigned* d, const unsigned* a, unsigned b0, unsigned b1) {
    asm("mma.sync.aligned.m16n8k16.row.col.f16.f16.f16.f16 "
        "{%0,%1},{%2,%3,%4,%5},{%6,%7},{%0,%1};"
        : "+r"(d[0]), "+r"(d[1])
        : "r"(a[0]), "r"(a[1]), "r"(a[2]), "r"(a[3]), "r"(b0), "r"(b1));
}
// f16 mma, f32 accum (attention PV + denominator)
__device__ __forceinline__ void mma16f(float* d, const unsigned* a, unsigned b0, unsigned b1) {
    asm("mma.sync.aligned.m16n8k16.row.col.f32.f16.f16.f32 "
        "{%0,%1,%2,%3},{%4,%5,%6,%7},{%8,%9},{%0,%1,%2,%3};"
        : "+f"(d[0]), "+f"(d[1]), "+f"(d[2]), "+f"(d[3])
        : "r"(a[0]), "r"(a[1]), "r"(a[2]), "r"(a[3]), "r"(b0), "r"(b1));
}
__device__ __forceinline__ void ldmx4(unsigned* r, unsigned addr) {
    asm volatile("ldmatrix.sync.aligned.m8n8.x4.shared.b16 {%0,%1,%2,%3}, [%4];"
        : "=r"(r[0]), "=r"(r[1]), "=r"(r[2]), "=r"(r[3]) : "r"(addr));
}
__device__ __forceinline__ void ldmx4t(unsigned* r, unsigned addr) {
    asm volatile("ldmatrix.sync.aligned.m8n8.x4.trans.shared.b16 {%0,%1,%2,%3}, [%4];"
        : "=r"(r[0]), "=r"(r[1]), "=r"(r[2]), "=r"(r[3]) : "r"(addr));
}
__device__ __forceinline__ void cp16s(unsigned s, const void* g) {
    asm volatile("cp.async.cg.shared.global [%0], [%1], 16;" :: "r"(s), "l"(g));
}
__device__ __forceinline__ void cp_commit() { asm volatile("cp.async.commit_group;"); }
__device__ __forceinline__ void cp_wait1()  { asm volatile("cp.async.wait_group 1;"); }
__device__ __forceinline__ void cp_wait0()  { asm volatile("cp.async.wait_group 0;"); }

// swizzled dst offset within a tile of 128B rows: chunk c (16B), row r
__device__ __forceinline__ unsigned swz(int r, int c) {
    return (unsigned)(r * 128 + ((c ^ (r & 7)) * 16));
}

// ---------------- prepasses ----------------
__global__ void cvt_hs_kernel(const float4* __restrict__ in) {
    int i = blockIdx.x * blockDim.x + threadIdx.x;   // over NROWS*CC/4
    float4 f = in[i];
    ((uint2*)g_X)[i] = make_uint2(bf16x2(f.y, f.x), bf16x2(f.w, f.z));
}

__global__ void build_ctx_kernel(const int* __restrict__ indices) {
    int bi = blockIdx.x;            // bi = s*5 + i
    int i  = bi % 5;
    int s  = bi / 5;
    for (int k = threadIdx.x; k < SCTX; k += blockDim.x) {
        int row;
        if (k < 2048) {
            int jp = k >> 9;
            int j  = jp + (jp >= i ? 1 : 0);
            row = (s * 5 + j) * 1024 + indices[j * 512 + (k & 511)];
        } else {
            row = bi * 1024 + (k - 2048);
        }
        g_ctx[bi * SCTX + k] = row;
    }
}

__global__ void transpose_kernel(const float* __restrict__ W0, const float* __restrict__ W1,
                                 const float* __restrict__ W2, const float* __restrict__ W3) {
    __shared__ float t[32][33];
    const int z = blockIdx.z;
    const float* src = z == 0 ? W0 : z == 1 ? W1 : z == 2 ? W2 : W3;
    __nv_bfloat16* dst = g_WT + (size_t)z * CC * CC;
    const int col  = blockIdx.x * 32 + threadIdx.x;
    const int row0 = blockIdx.y * 32;
    #pragma unroll
    for (int i = 0; i < 4; ++i)
        t[threadIdx.y + i * 8][threadIdx.x] = src[(size_t)(row0 + threadIdx.y + i * 8) * CC + col];
    __syncthreads();
    const int k = row0 + threadIdx.x;
    #pragma unroll
    for (int i = 0; i < 4; ++i)
        dst[(size_t)(blockIdx.x * 32 + threadIdx.y + i * 8) * CC + k] =
            __float2bfloat16(t[threadIdx.x][threadIdx.y + i * 8]);
}

// ---------------- bf16 mma GEMM: Y[M,N] = A[M,:] . WT[N,:]^T ----------------
// BM=128, BN=128, BK=64 (128B rows, SW128); 8 warps (4m x 2n), warp tile 32x64;
// 3-stage cp.async ring, one barrier per iteration; ldmatrix fragment loads.
// MODE 0 = f32 + bias + residual; MODE 1 = fp16 out.
static constexpr int GEMM_SMEM = 3 * 2 * 128 * 128;   // 98304 B

template<int MODE>
__device__ __forceinline__ void gemm_body(const __nv_bfloat16* __restrict__ A,
                                          const __nv_bfloat16* __restrict__ Bt,
                                          float* __restrict__ Yf,
                                          __half* __restrict__ Yh,
                                          const float* __restrict__ bias,
                                          const float* __restrict__ res,
                                          float scale) {
    extern __shared__ __align__(16) char smc[];
    const unsigned sbase = (unsigned)__cvta_generic_to_shared(smc);
    const int tid = threadIdx.x, lane = tid & 31, wid = tid >> 5;
    const int wm = wid >> 1, wn = wid & 1;
    const int lg = lane >> 2, lc = lane & 3;
    const int m0 = blockIdx.y << 7, n0 = blockIdx.x << 7;

    float acc[2][8][4];
    #pragma unroll
    for (int mt = 0; mt < 2; ++mt)
        #pragma unroll
        for (int nt = 0; nt < 8; ++nt)
            #pragma unroll
            for (int q = 0; q < 4; ++q) acc[mt][nt][q] = 0.f;

    auto load = [&](int buf, int k0) {   // k0 in bf16 elems
        const unsigned sA = sbase + (unsigned)buf * 32768u;
        const unsigned sB = sA + 16384u;
        #pragma unroll
        for (int i = 0; i < 4; ++i) {
            const int idx = tid + i * 256;
            const int row = idx >> 3, c = idx & 7;
            const unsigned so = swz(row, c);
            cp16s(sA + so, A  + (size_t)(m0 + row) * CC + k0 + c * 8);
            cp16s(sB + so, Bt + (size_t)(n0 + row) * CC + k0 + c * 8);
        }
        cp_commit();
    };

    load(0, 0);
    load(1, 64);

    // per-warp fragment address components
    const int arow = wm * 32 + (lane & 15);
    const int ach  = lane >> 4;
    const int brow = wn * 64 + ((lane >> 4) << 3) + (lane & 7);
    const int bch  = (lane >> 3) & 1;

    for (int it = 0; it < 20; ++it) {
        const int b = it % 3;
        if (it == 19) cp_wait0(); else cp_wait1();
        __syncthreads();                       // stage it ready; buffer (it+2)%3 free
        if (it + 2 < 20) load((it + 2) % 3, (it + 2) * 64);
        const unsigned aB = sbase + (unsigned)b * 32768u;
        const unsigned bB = aB + 16384u;
        #pragma unroll
        for (int ks = 0; ks < 4; ++ks) {
            unsigned af[2][4], bf[4][4];
            #pragma unroll
            for (int mt = 0; mt < 2; ++mt)
                ldmx4(af[mt], aB + swz(arow + mt * 16, 2 * ks + ach));
            #pragma unroll
            for (int g = 0; g < 4; ++g)
                ldmx4(bf[g], bB + swz(brow + g * 16, 2 * ks + bch));
            #pragma unroll
            for (int mt = 0; mt < 2; ++mt)
                #pragma unroll
                for (int g = 0; g < 4; ++g) {
                    mma16(acc[mt][2 * g],     af[mt], bf[g][0], bf[g][1]);
                    mma16(acc[mt][2 * g + 1], af[mt], bf[g][2], bf[g][3]);
                }
        }
    }

    #pragma unroll
    for (int mt = 0; mt < 2; ++mt) {
        const int r0 = m0 + wm * 32 + mt * 16 + lg;
        #pragma unroll
        for (int nt = 0; nt < 8; ++nt) {
            const int n = n0 + wn * 64 + nt * 8 + 2 * lc;
            float v0 = acc[mt][nt][0] * scale, v1 = acc[mt][nt][1] * scale;
            float v2 = acc[mt][nt][2] * scale, v3 = acc[mt][nt][3] * scale;
            if (MODE == 0) {
                const float2 b0 = *(const float2*)&bias[n];
                const float2 u0 = *(const float2*)&res[(size_t)r0 * CC + n];
                const float2 u1 = *(const float2*)&res[(size_t)(r0 + 8) * CC + n];
                *(float2*)&Yf[(size_t)r0 * CC + n]       = make_float2(v0 + b0.x + u0.x, v1 + b0.y + u0.y);
                *(float2*)&Yf[(size_t)(r0 + 8) * CC + n] = make_float2(v2 + b0.x + u1.x, v3 + b0.y + u1.y);
            } else {
                *(unsigned*)&Yh[(size_t)r0 * CC + n]       = f16x2(v1, v0);
                *(unsigned*)&Yh[(size_t)(r0 + 8) * CC + n] = f16x2(v3, v2);
            }
        }
    }
}

__global__ __launch_bounds__(256, 2) void gemm_qkv_kernel() {
    const int z = blockIdx.z;
    const __nv_bfloat16* WT = g_WT + (size_t)z * CC * CC;
    __half* Y = z == 0 ? g_Q : z == 1 ? g_K : g_V;
    // Q carries 0.125 * log2(e) so attention can use raw ex2
    gemm_body<1>(g_X, WT, nullptr, Y, nullptr, nullptr, z == 0 ? QSCALE : 1.0f);
}

__global__ __launch_bounds__(256, 2) void gemm_out_kernel(float* __restrict__ Y,
                                                          const float* __restrict__ bias,
                                                          const float* __restrict__ res) {
    gemm_body<0>((const __nv_bfloat16*)g_O, g_WT + 3 * (size_t)CC * CC, Y, nullptr, bias, res, 1.0f);
}

// ---------------- gathered flash attention: fp16 mma, two-tile fused scheduling ----------------
// grid (8 q-blocks, 20 heads, 10 (side,image)); 256 threads = 8 warps; warp: 16 q rows.
// BQ=128, BKEY=64, hd=64. 4-stage KV ring, two tiles per barrier, and BOTH tiles'
// S / P / PV phases emitted in one straight-line region so ptxas can overlap one
// tile's ex2 (MUFU) latency with the other tile's tensor mmas.
// Logits in log2 domain; P = ex2.f16x2 on accumulator regs; denominator via ones-MMA.
static constexpr int ATTN_SMEM = (128 + 4 * 128) * 128;   // Q + 4*(K+V) = 81920 B

__global__ __launch_bounds__(256, 2) void attn_kernel() {
    extern __shared__ __align__(16) char smc[];
    const unsigned sQ   = (unsigned)__cvta_generic_to_shared(smc);
    const unsigned sKV0 = sQ + 16384u;        // stage s: K at +s*16384, V at +s*16384+8192

    const int tid = threadIdx.x, lane = tid & 31, wid = tid >> 5;
    const int lg = lane >> 2, lc = lane & 3;
    const int qb = blockIdx.x, h = blockIdx.y, bi = blockIdx.z;
    const int r0 = bi * 1024 + (qb << 7);
    const int hc = h << 6;
    const int* ctx = g_ctx + bi * SCTX;
    const unsigned ONESH = 0x3C003C00u;       // f16x2 {1.0, 1.0}

    // Q tile load: 128 rows x 8 chunks; 2 threads/row, 4 chunks each
    {
        const int r = tid >> 1, c0 = (tid & 1) * 4;
        const __half* gq = g_Q + (size_t)(r0 + r) * CC + hc;
        #pragma unroll
        for (int j = 0; j < 4; ++j)
            cp16s(sQ + swz(r, c0 + j), gq + (c0 + j) * 8);
    }
    // K/V tile gather: 64 rows x 8 chunks; 4 threads/row, 2+2 chunks each
    auto loadKV = [&](int buf, int kt) {
        const unsigned kB = sKV0 + (unsigned)buf * 16384u;
        const unsigned vB = kB + 8192u;
        const int r = tid >> 2, c = tid & 3;
        const int krow = ctx[(kt << 6) + r];
        const size_t gb = (size_t)krow * CC + hc;
        cp16s(kB + swz(r, c),     g_K + gb + c * 8);
        cp16s(kB + swz(r, c + 4), g_K + gb + (c + 4) * 8);
        cp16s(vB + swz(r, c),     g_V + gb + c * 8);
        cp16s(vB + swz(r, c + 4), g_V + gb + (c + 4) * 8);
        cp_commit();
    };
    loadKV(0, 0);       // Q rides in group 0
    loadKV(1, 1);

    float oacc[8][4];
    #pragma unroll
    for (int nt = 0; nt < 8; ++nt)
        #pragma unroll
        for (int q = 0; q < 4; ++q) oacc[nt][q] = 0.f;
    float lacc[4] = {0.f, 0.f, 0.f, 0.f};     // ones-mma denominator accumulator
    unsigned qf[4][4];

    // fragment address components
    const int qrow = wid * 16 + (lane & 15);
    const int qch  = lane >> 4;
    const int krow = ((lane >> 4) << 3) + (lane & 7);
    const int kch  = (lane >> 3) & 1;
    const int vrow = ((lane >> 3) & 1) * 8 + (lane & 7);
    const int vch  = lane >> 4;

    // S-phase for one tile: s2[8][2] f16x2 accumulators
    auto s_phase = [&](unsigned kB, unsigned (&s2)[8][2]) {
        #pragma unroll
        for (int g = 0; g < 8; ++g) { s2[g][0] = 0u; s2[g][1] = 0u; }
        #pragma unroll
        for (int ks = 0; ks < 4; ++ks) {
            #pragma unroll
            for (int g = 0; g < 4; ++g) {
                unsigned kf[4];
                ldmx4(kf, kB + swz(g * 16 + krow, 2 * ks + kch));
                mma16h(s2[2 * g],     qf[ks], kf[0], kf[1]);
                mma16h(s2[2 * g + 1], qf[ks], kf[2], kf[3]);
            }
        }
    };
    // P-phase: ex2 on accumulators (layout already matches PV A-frags) + ones-MMA denominator
    auto p_phase = [&](const unsigned (&s2)[8][2], unsigned (&pf)[4][4]) {
        #pragma unroll
        for (int s = 0; s < 4; ++s) {
            pf[s][0] = ex2h2(s2[2 * s][0]);
            pf[s][1] = ex2h2(s2[2 * s][1]);
            pf[s][2] = ex2h2(s2[2 * s + 1][0]);
            pf[s][3] = ex2h2(s2[2 * s + 1][1]);
            mma16f(lacc, pf[s], ONESH, ONESH);
        }
    };
    // PV-phase
    auto pv_phase = [&](unsigned vB, const unsigned (&pf)[4][4]) {
        #pragma unroll
        for (int s = 0; s < 4; ++s) {
            #pragma unroll
            for (int g = 0; g < 4; ++g) {
                unsigned vf[4];
                ldmx4t(vf, vB + swz(s * 16 + vrow, 2 * g + vch));
                mma16f(oacc[2 * g],     pf[s], vf[0], vf[1]);
                mma16f(oacc[2 * g + 1], pf[s], vf[2], vf[3]);
            }
        }
    };

    // 24 iterations, 2 tiles each, ONE barrier per iteration; both tiles' phases
    // in one region so the scheduler overlaps MUFU latency with tensor issue.
    for (int j = 0; j < 24; ++j) {
        cp_wait0();
        __syncthreads();
        if (j == 0) {                     // Q arrived with tile 0 — hoist fragments once
            #pragma unroll
            for (int ks = 0; ks < 4; ++ks)
                ldmx4(qf[ks], sQ + swz(qrow, 2 * ks + qch));
        }
        if (j + 1 < 24) {
            loadKV((2 * j + 2) & 3, 2 * j + 2);
            loadKV((2 * j + 3) & 3, 2 * j + 3);
        }
        const unsigned kA = sKV0 + (unsigned)((2 * j) & 3) * 16384u;
        const unsigned kBt = sKV0 + (unsigned)((2 * j + 1) & 3) * 16384u;

        unsigned s2a[8][2], s2b[8][2];
        s_phase(kA,  s2a);
        s_phase(kBt, s2b);                 // independent — fills tensor pipe
        unsigned pfa[4][4], pfb[4][4];
        p_phase(s2a, pfa);                 // ex2(A) overlaps tail of S(B)
        p_phase(s2b, pfb);
        pv_phase(kA + 8192u,  pfa);
        pv_phase(kBt + 8192u, pfb);
    }

    // ---- normalize + store O (bf16); denominator complete per-lane ----
    const float inv0 = 1.0f / lacc[0], inv1 = 1.0f / lacc[2];
    const int qr = r0 + wid * 16 + lg;
    #pragma unroll
    for (int nt = 0; nt < 8; ++nt) {
        const int n = hc + nt * 8 + 2 * lc;
        *(unsigned*)&g_O[(size_t)qr * CC + n] =
            bf16x2(oacc[nt][1] * inv0, oacc[nt][0] * inv0);
        *(unsigned*)&g_O[(size_t)(qr + 8) * CC + n] =
            bf16x2(oacc[nt][3] * inv1, oacc[nt][2] * inv1);
    }
}

// ---------------- launcher ----------------
extern "C" void kernel_launch(void* const* d_in, const int* in_sizes, int n_in,
                              void* d_out, int out_size) {
    const float* hs  = (const float*)d_in[0];
    const int*   idx = (const int*)  d_in[1];
    const float* Wq  = (const float*)d_in[2];
    const float* Wk  = (const float*)d_in[3];
    const float* Wv  = (const float*)d_in[4];
    const float* Wo  = (const float*)d_in[5];
    const float* bo  = (const float*)d_in[6];
    float* out = (float*)d_out;

    cudaFuncSetAttribute(gemm_qkv_kernel, cudaFuncAttributeMaxDynamicSharedMemorySize, GEMM_SMEM);
    cudaFuncSetAttribute(gemm_out_kernel, cudaFuncAttributeMaxDynamicSharedMemorySize, GEMM_SMEM);
    cudaFuncSetAttribute(attn_kernel,     cudaFuncAttributeMaxDynamicSharedMemorySize, ATTN_SMEM);

    cvt_hs_kernel<<<(NROWS * CC / 4) / 256, 256>>>((const float4*)hs);
    transpose_kernel<<<dim3(CC / 32, CC / 32, 4), dim3(32, 8)>>>(Wq, Wk, Wv, Wo);
    build_ctx_kernel<<<10, 256>>>(idx);

    gemm_qkv_kernel<<<dim3(CC / 128, NROWS / 128, 3), 256, GEMM_SMEM>>>();

    attn_kernel<<<dim3(8, 20, 10), 256, ATTN_SMEM>>>();

    gemm_out_kernel<<<dim3(CC / 128, NROWS / 128), 256, GEMM_SMEM>>>(out, bo, hs);
}